// round 2
// baseline (speedup 1.0000x reference)
#include <cuda_runtime.h>
#include <math_constants.h>

#define HN 512    // hidden states
#define HM 4096   // emission symbols
#define HB 64     // batch
#define HT 512    // max sequence length
#define BT 16     // batch tile in step kernel
#define JT 16     // state tile in step kernel

// Scratch (device globals: allocation-free contract)
__device__ float    g_ET[HM * HN];          // 8MB  : E_T[m][n] = log p(x=m | state n)
__device__ float    g_TR[HN * HN];          // 1MB  : TR[j][k] = p(j | k)  (j-major)
__device__ float    g_alpha[HT * HB * HN];  // 64MB : alpha[t][b][j]
__device__ unsigned g_m[HT * HB];           // encoded per-(t,b) max of alpha

// ---- order-preserving float <-> uint encoding for atomicMax ----
__device__ __forceinline__ unsigned encf(float f) {
    unsigned u = __float_as_uint(f);
    return (u & 0x80000000u) ? ~u : (u | 0x80000000u);
}
__device__ __forceinline__ float decf(unsigned k) {
    unsigned u = (k & 0x80000000u) ? (k ^ 0x80000000u) : ~k;
    return __uint_as_float(u);
}

// ---- block reductions ----
__device__ __forceinline__ float warpMax(float v) {
#pragma unroll
    for (int o = 16; o > 0; o >>= 1) v = fmaxf(v, __shfl_xor_sync(0xffffffffu, v, o));
    return v;
}
__device__ __forceinline__ float warpSum(float v) {
#pragma unroll
    for (int o = 16; o > 0; o >>= 1) v += __shfl_xor_sync(0xffffffffu, v, o);
    return v;
}
__device__ __forceinline__ float blkMax(float v, float* s32) {
    __syncthreads();
    v = warpMax(v);
    int lane = threadIdx.x & 31, wid = threadIdx.x >> 5;
    if (lane == 0) s32[wid] = v;
    __syncthreads();
    int nw = blockDim.x >> 5;
    float r = (threadIdx.x < (unsigned)nw) ? s32[threadIdx.x] : -CUDART_INF_F;
    if (wid == 0) { r = warpMax(r); if (lane == 0) s32[0] = r; }
    __syncthreads();
    return s32[0];
}
__device__ __forceinline__ float blkSum(float v, float* s32) {
    __syncthreads();
    v = warpSum(v);
    int lane = threadIdx.x & 31, wid = threadIdx.x >> 5;
    if (lane == 0) s32[wid] = v;
    __syncthreads();
    int nw = blockDim.x >> 5;
    float r = (threadIdx.x < (unsigned)nw) ? s32[threadIdx.x] : 0.0f;
    if (wid == 0) { r = warpSum(r); if (lane == 0) s32[0] = r; }
    __syncthreads();
    return s32[0];
}

// ---- precompute: E_T[m][n] = emission[n][m] - logsumexp_m ----
__global__ void k_em(const float* __restrict__ em) {
    int n = blockIdx.x;          // state row
    int tid = threadIdx.x;       // 256 threads
    __shared__ float s32[32];
    const float* row = em + n * HM;
    float v[16];
    float mx = -CUDART_INF_F;
#pragma unroll
    for (int i = 0; i < 16; i++) { v[i] = row[tid + i * 256]; mx = fmaxf(mx, v[i]); }
    mx = blkMax(mx, s32);
    float sm = 0.0f;
#pragma unroll
    for (int i = 0; i < 16; i++) sm += __expf(v[i] - mx);
    sm = blkSum(sm, s32);
    float lse = mx + __logf(sm);
#pragma unroll
    for (int i = 0; i < 16; i++) g_ET[(tid + i * 256) * HN + n] = v[i] - lse;
}

// ---- precompute: TR[j][k] = softmax over j of transition[j][k]; also zero g_m ----
__global__ void k_tr(const float* __restrict__ tr) {
    int k = blockIdx.x;          // column
    int j = threadIdx.x;         // 512 threads
    __shared__ float s32[32];
    float v = tr[j * HN + k];
    float mx = blkMax(v, s32);
    float sm = blkSum(__expf(v - mx), s32);
    float lse = mx + __logf(sm);
    g_TR[j * HN + k] = __expf(v - lse);
    if (j < HB) g_m[k * HB + j] = 0u;   // blockIdx.x covers all HT rows (HT==HN)
}

// ---- init: alpha0 = obs0 + log_prior; m[0][b] = max ----
__global__ void k_init(const int* __restrict__ x, const float* __restrict__ pri) {
    int b = blockIdx.x;
    int j = threadIdx.x;         // 512 threads
    __shared__ float s32[32];
    float p = pri[j];
    float mx = blkMax(p, s32);
    float sm = blkSum(__expf(p - mx), s32);
    float lsep = mx + __logf(sm);
    int xv = x[b * HT + 0];
    float a = g_ET[xv * HN + j] + (p - lsep);
    g_alpha[b * HN + j] = a;
    float am = blkMax(a, s32);
    if (j == 0) g_m[b] = encf(am);
}

// ---- one recurrence step: alpha_t = obs_t + m + log( w @ TR^T ) ----
__global__ void __launch_bounds__(BT * JT) k_step(const int* __restrict__ x, int t) {
    __shared__ float w_s[BT][HN + 4];    // padded: conflict-free LDS.128
    __shared__ float m_s[BT];
    __shared__ float red[BT][JT + 1];
    int b0 = blockIdx.y * BT;
    int j0 = blockIdx.x * JT;
    int tid = threadIdx.x;               // 256

    if (tid < BT) m_s[tid] = decf(g_m[(t - 1) * HB + b0 + tid]);
    __syncthreads();

    const float* aprev = g_alpha + (size_t)(t - 1) * HB * HN;
    for (int i = tid; i < BT * HN; i += BT * JT) {
        int bb = i >> 9, kk = i & (HN - 1);
        w_s[bb][kk] = __expf(aprev[(b0 + bb) * HN + kk] - m_s[bb]);
    }
    __syncthreads();

    int bb = tid & (BT - 1);
    int jj = tid >> 4;
    int j = j0 + jj;
    const float4* tr4 = reinterpret_cast<const float4*>(g_TR + j * HN);  // L1-broadcast across bb
    const float4* w4  = reinterpret_cast<const float4*>(&w_s[bb][0]);
    float a0 = 0.f, a1 = 0.f, a2 = 0.f, a3 = 0.f;
#pragma unroll 8
    for (int kq = 0; kq < HN / 4; kq++) {
        float4 tv = tr4[kq];
        float4 wv = w4[kq];
        a0 = fmaf(tv.x, wv.x, a0);
        a1 = fmaf(tv.y, wv.y, a1);
        a2 = fmaf(tv.z, wv.z, a2);
        a3 = fmaf(tv.w, wv.w, a3);
    }
    float s = (a0 + a1) + (a2 + a3);

    int b = b0 + bb;
    int xv = x[b * HT + t];
    float na = g_ET[xv * HN + j] + m_s[bb] + __logf(s);
    g_alpha[((size_t)t * HB + b) * HN + j] = na;

    red[bb][jj] = na;
    __syncthreads();
    if (tid < BT) {
        float mx = red[tid][0];
#pragma unroll
        for (int q = 1; q < JT; q++) mx = fmaxf(mx, red[tid][q]);
        atomicMax(&g_m[t * HB + tid + b0], encf(mx));
    }
}

// ---- output: out[b] = logsumexp_j alpha[T[b]-1][b][:] ----
__global__ void k_out(const int* __restrict__ T, float* __restrict__ out) {
    int b = blockIdx.x;
    int j = threadIdx.x;         // 512 threads
    __shared__ float s32[32];
    int tb = T[b] - 1;
    float a = g_alpha[((size_t)tb * HB + b) * HN + j];
    float mx = blkMax(a, s32);
    float sm = blkSum(__expf(a - mx), s32);
    if (j == 0) out[b] = mx + __logf(sm);
}

extern "C" void kernel_launch(void* const* d_in, const int* in_sizes, int n_in,
                              void* d_out, int out_size) {
    const int*   x   = (const int*)d_in[0];
    const int*   T   = (const int*)d_in[1];
    const float* em  = (const float*)d_in[2];
    const float* tr  = (const float*)d_in[3];
    const float* pri = (const float*)d_in[4];
    float* out = (float*)d_out;

    k_em<<<HN, 256>>>(em);
    k_tr<<<HN, HN>>>(tr);
    k_init<<<HB, HN>>>(x, pri);
    dim3 grid(HN / JT, HB / BT);   // 32 x 4 = 128 blocks
    for (int t = 1; t < HT; t++) {
        k_step<<<grid, BT * JT>>>(x, t);
    }
    k_out<<<HB, HN>>>(T, out);
}

// round 3
// speedup vs baseline: 2.1912x; 2.1912x over previous
#include <cuda_runtime.h>
#include <math_constants.h>

#define HN 512    // hidden states
#define HM 4096   // emission symbols
#define HB 64     // batch
#define HT 512    // max sequence length

#define NBLK 128          // persistent grid: 16 j-tiles x 8 b-tiles
#define JTILE 32          // j per block
#define BTILE 8           // b per block
#define NTHR 256
#define ROWP 516          // padded row stride (floats): conflict-free smem

// ---- device scratch (allocation-free contract) ----
__device__ float g_ET[HM * HN];         // 8MB : ET[m][n] = log p(x=m | state n)
__device__ float g_TR[HN * HN];         // 1MB : TR[j][k] = p(j|k), j-major
__device__ float g_alpha[2 * HB * HN];  // ping-pong alpha slices
__device__ float g_final[HB * HN];      // alpha at t = T[b]-1
__device__ unsigned g_count = 0;        // grid barrier
__device__ unsigned g_gen = 0;

// ---- packed f32x2 fma (sm_103a FFMA2) ----
__device__ __forceinline__ void ffma2(unsigned long long& d,
                                      unsigned long long a,
                                      unsigned long long b) {
    asm("fma.rn.f32x2 %0, %1, %2, %0;" : "+l"(d) : "l"(a), "l"(b));
}
__device__ __forceinline__ float2 u2f(unsigned long long v) {
    float2 r;
    asm("mov.b64 {%0,%1}, %2;" : "=f"(r.x), "=f"(r.y) : "l"(v));
    return r;
}

// ---- block reductions (precompute kernels only) ----
__device__ __forceinline__ float warpMax(float v) {
#pragma unroll
    for (int o = 16; o > 0; o >>= 1) v = fmaxf(v, __shfl_xor_sync(0xffffffffu, v, o));
    return v;
}
__device__ __forceinline__ float warpSum(float v) {
#pragma unroll
    for (int o = 16; o > 0; o >>= 1) v += __shfl_xor_sync(0xffffffffu, v, o);
    return v;
}
__device__ __forceinline__ float blkMax(float v, float* s32) {
    __syncthreads();
    v = warpMax(v);
    int lane = threadIdx.x & 31, wid = threadIdx.x >> 5;
    if (lane == 0) s32[wid] = v;
    __syncthreads();
    int nw = blockDim.x >> 5;
    float r = (threadIdx.x < (unsigned)nw) ? s32[threadIdx.x] : -CUDART_INF_F;
    if (wid == 0) { r = warpMax(r); if (lane == 0) s32[0] = r; }
    __syncthreads();
    return s32[0];
}
__device__ __forceinline__ float blkSum(float v, float* s32) {
    __syncthreads();
    v = warpSum(v);
    int lane = threadIdx.x & 31, wid = threadIdx.x >> 5;
    if (lane == 0) s32[wid] = v;
    __syncthreads();
    int nw = blockDim.x >> 5;
    float r = (threadIdx.x < (unsigned)nw) ? s32[threadIdx.x] : 0.0f;
    if (wid == 0) { r = warpSum(r); if (lane == 0) s32[0] = r; }
    __syncthreads();
    return s32[0];
}

// ---- precompute: ET[m][n] = emission[n][m] - logsumexp_m ----
__global__ void k_em(const float* __restrict__ em) {
    int n = blockIdx.x;
    int tid = threadIdx.x;  // 256
    __shared__ float s32[32];
    const float* row = em + n * HM;
    float v[16];
    float mx = -CUDART_INF_F;
#pragma unroll
    for (int i = 0; i < 16; i++) { v[i] = row[tid + i * 256]; mx = fmaxf(mx, v[i]); }
    mx = blkMax(mx, s32);
    float sm = 0.0f;
#pragma unroll
    for (int i = 0; i < 16; i++) sm += __expf(v[i] - mx);
    sm = blkSum(sm, s32);
    float lse = mx + __logf(sm);
#pragma unroll
    for (int i = 0; i < 16; i++) g_ET[(tid + i * 256) * HN + n] = v[i] - lse;
}

// ---- precompute: TR[j][k] = softmax_j(transition[j][k]) ----
__global__ void k_tr(const float* __restrict__ tr) {
    int k = blockIdx.x;
    int j = threadIdx.x;  // 512
    __shared__ float s32[32];
    float v = tr[j * HN + k];
    float mx = blkMax(v, s32);
    float sm = blkSum(__expf(v - mx), s32);
    float lse = mx + __logf(sm);
    g_TR[j * HN + k] = __expf(v - lse);
}

// ---- init: alpha0 = obs0 + log_prior (slot 0); g_final default = alpha0 ----
__global__ void k_init(const int* __restrict__ x, const float* __restrict__ pri) {
    int b = blockIdx.x;
    int j = threadIdx.x;  // 512
    __shared__ float s32[32];
    float p = pri[j];
    float mx = blkMax(p, s32);
    float sm = blkSum(__expf(p - mx), s32);
    float lsep = mx + __logf(sm);
    int xv = x[b * HT + 0];
    float a = g_ET[xv * HN + j] + (p - lsep);
    g_alpha[b * HN + j] = a;
    g_final[b * HN + j] = a;   // stands if T[b]==1
}

// ---- grid barrier (all NBLK blocks co-resident) ----
__device__ __forceinline__ void grid_sync() {
    __threadfence();
    __syncthreads();
    if (threadIdx.x == 0) {
        unsigned gen = *((volatile unsigned*)&g_gen);
        unsigned t = atomicAdd(&g_count, 1u);
        if (t == NBLK - 1) {
            *((volatile unsigned*)&g_count) = 0u;
            __threadfence();
            *((volatile unsigned*)&g_gen) = gen + 1u;
        } else {
            while (*((volatile unsigned*)&g_gen) == gen) { __nanosleep(32); }
        }
        __threadfence();
    }
    __syncthreads();
}

// ---- persistent recurrence kernel: all 511 steps in one launch ----
__global__ void __launch_bounds__(NTHR, 1) k_persist(const int* __restrict__ x,
                                                     const int* __restrict__ Tlen) {
    extern __shared__ float smem[];
    float* TRS = smem;                         // JTILE x ROWP
    float* WS  = TRS + JTILE * ROWP;           // BTILE x ROWP
    float* RED = WS + BTILE * ROWP;            // 2 x 256
    float* OS  = RED + 512;                    // BTILE offsets
    int*   XS  = (int*)(OS + BTILE);           // BTILE obs symbols
    int*   TS  = XS + BTILE;                   // BTILE lengths

    int tid = threadIdx.x;
    int jt = blockIdx.x & 15;
    int bt = blockIdx.x >> 4;
    int j0 = jt * JTILE;
    int b0 = bt * BTILE;

    // prologue: pin TR slice in smem (once), load T values
    {
        const float4* tr4 = reinterpret_cast<const float4*>(g_TR);
        float4* trs4 = reinterpret_cast<float4*>(TRS);
#pragma unroll
        for (int q = 0; q < (JTILE * HN / 4) / NTHR; q++) {
            int idx = tid + q * NTHR;
            int r = idx >> 7;           // local j row
            int kq = idx & 127;
            trs4[r * (ROWP / 4) + kq] = tr4[(size_t)(j0 + r) * (HN / 4) + kq];
        }
        if (tid < BTILE) TS[tid] = Tlen[b0 + tid];
    }
    __syncthreads();

    const int bb = tid & 7;
    const int jp = (tid >> 3) & 15;
    const int ks = tid >> 7;
    const int jl0 = 2 * jp;

    for (int t = 1; t < HT; t++) {
        const float* aprev = g_alpha + ((t - 1) & 1) * HB * HN;
        float*       acur  = g_alpha + (t & 1) * HB * HN;

        // per-batch offset (any value near max works) + obs symbol
        if (tid < BTILE) {
            OS[tid] = __ldcg(aprev + (b0 + tid) * HN);   // alpha_prev[b][0]
            XS[tid] = x[(b0 + tid) * HT + t];
        }
        __syncthreads();

        // w = exp(alpha_prev - o)  (L1-bypass: ping-pong buffer written by other SMs)
        {
            const float4* ap4 = reinterpret_cast<const float4*>(aprev + b0 * HN);
            float4* ws4 = reinterpret_cast<float4*>(WS);
#pragma unroll
            for (int q = 0; q < (BTILE * HN / 4) / NTHR; q++) {
                int idx = tid + q * NTHR;
                int br = idx >> 7;
                int kq = idx & 127;
                float4 a = __ldcg(ap4 + br * (HN / 4) + kq);
                float o = OS[br];
                float4 w;
                w.x = __expf(a.x - o); w.y = __expf(a.y - o);
                w.z = __expf(a.z - o); w.w = __expf(a.w - o);
                ws4[br * (ROWP / 4) + kq] = w;
            }
        }
        __syncthreads();

        // dot: 2 outputs (bb, j0..j0+1), half of k (ks)
        {
            const ulonglong2* t0p = reinterpret_cast<const ulonglong2*>(TRS + jl0 * ROWP) + ks * 64;
            const ulonglong2* t1p = t0p + (ROWP / 4);
            const ulonglong2* wp  = reinterpret_cast<const ulonglong2*>(WS + bb * ROWP) + ks * 64;
            unsigned long long a0l = 0, a0h = 0, a1l = 0, a1h = 0;
#pragma unroll 8
            for (int i = 0; i < 64; i++) {
                ulonglong2 T0 = t0p[i];
                ulonglong2 T1 = t1p[i];
                ulonglong2 W  = wp[i];
                ffma2(a0l, T0.x, W.x);
                ffma2(a0h, T0.y, W.y);
                ffma2(a1l, T1.x, W.x);
                ffma2(a1h, T1.y, W.y);
            }
            float2 f;
            float s0, s1;
            f = u2f(a0l); s0 = f.x + f.y;
            f = u2f(a0h); s0 += f.x + f.y;
            f = u2f(a1l); s1 = f.x + f.y;
            f = u2f(a1h); s1 += f.x + f.y;
            int o = bb * 32 + jl0;
            RED[ks * 256 + o]     = s0;
            RED[ks * 256 + o + 1] = s1;
        }
        __syncthreads();

        // combine k-halves, epilogue, store
        {
            int o = tid;                 // 0..255 outputs
            float s = RED[o] + RED[256 + o];
            int obb = o >> 5;
            int jl = o & 31;
            int b = b0 + obb;
            int j = j0 + jl;
            float na = g_ET[(size_t)XS[obb] * HN + j] + OS[obb] + __logf(s);
            __stcg(acur + b * HN + j, na);
            if (t == TS[obb] - 1) g_final[b * HN + j] = na;
        }

        grid_sync();
    }
}

// ---- output: out[b] = logsumexp_j g_final[b][:] ----
__global__ void k_out(float* __restrict__ out) {
    int b = blockIdx.x;
    int j = threadIdx.x;  // 512
    __shared__ float s32[32];
    float a = g_final[b * HN + j];
    float mx = blkMax(a, s32);
    float sm = blkSum(__expf(a - mx), s32);
    if (j == 0) out[b] = mx + __logf(sm);
}

extern "C" void kernel_launch(void* const* d_in, const int* in_sizes, int n_in,
                              void* d_out, int out_size) {
    const int*   x   = (const int*)d_in[0];
    const int*   T   = (const int*)d_in[1];
    const float* em  = (const float*)d_in[2];
    const float* tr  = (const float*)d_in[3];
    const float* pri = (const float*)d_in[4];
    float* out = (float*)d_out;

    const int SMEM_BYTES = (JTILE * ROWP + BTILE * ROWP + 512 + BTILE) * 4 + 2 * BTILE * 4 + 64;
    static bool attr_done = false;
    if (!attr_done) {
        cudaFuncSetAttribute(k_persist, cudaFuncAttributeMaxDynamicSharedMemorySize, SMEM_BYTES);
        attr_done = true;
    }

    k_em<<<HN, 256>>>(em);
    k_tr<<<HN, HN>>>(tr);
    k_init<<<HB, HN>>>(x, pri);
    k_persist<<<NBLK, NTHR, SMEM_BYTES>>>(x, T);
    k_out<<<HB, HN>>>(out);
}